// round 15
// baseline (speedup 1.0000x reference)
#include <cuda_runtime.h>

#define MBN  10
#define BPC  3                 // batches per CTA (one warp)
#define NTHR 32

typedef unsigned long long u64;

__device__ __forceinline__ u64 fma2(u64 a, u64 b, u64 c){
    u64 d; asm("fma.rn.f32x2 %0, %1, %2, %3;" : "=l"(d) : "l"(a), "l"(b), "l"(c)); return d;
}
__device__ __forceinline__ u64 add2(u64 a, u64 b){
    u64 d; asm("add.rn.f32x2 %0, %1, %2;" : "=l"(d) : "l"(a), "l"(b)); return d;
}
__device__ __forceinline__ u64 packs(float x){
    u64 r; asm("mov.b64 %0, {%1, %1};" : "=l"(r) : "f"(x)); return r;
}
__device__ __forceinline__ u64 packp(float lo, float hi){
    u64 r; asm("mov.b64 %0, {%1, %2};" : "=l"(r) : "f"(lo), "f"(hi)); return r;
}
__device__ __forceinline__ void unpk(u64 v, float& lo, float& hi){
    asm("mov.b64 {%0, %1}, %2;" : "=f"(lo), "=f"(hi) : "l"(v));
}
__device__ __forceinline__ float hadd2(u64 v){
    float lo, hi; unpk(v, lo, hi); return lo + hi;
}

struct __align__(16) Sh {
    u64   part2[2][4][5][10];  // [buf][slot][mp][j]  kcv partials (double buffered)
    float psum[2][4][12];      // [buf][slot] APL partials
    float Wc[MBN][28];         // [m]: wddT[10] | wmdT[10] | pad
    float dec[2][12];          // decoder rows
};

__global__ void __launch_bounds__(NTHR, 12) fly_kernel(
    const float* __restrict__ odor,  const float* __restrict__ ctx,
    const float* __restrict__ pn_w,  const float* __restrict__ kn_b,
    const float* __restrict__ apl_w, const float* __restrict__ apl_b,
    const float* __restrict__ Wdm,   const float* __restrict__ mb_b,
    const float* __restrict__ Wmd,   const float* __restrict__ Wdd,
    const float* __restrict__ Wcd,   const float* __restrict__ dan_b,
    const float* __restrict__ decW,  const float* __restrict__ decB,
    const float* __restrict__ kw0,   const float* __restrict__ wa0,
    float* __restrict__ out, int Bn, int T)
{
    __shared__ Sh sh;
    const int tid  = threadIdx.x;
    const int m    = tid % MBN;            // m-role AND k-group index
    const int blL  = tid / MBN;            // 0..2 real, 3 dummy
    const int slot = blL;
    const int slotR= (blL == 3) ? 0 : blL;
    const bool wrp = (blL < 3);            // dummy lanes skip smem stores
    const int base = blL * 10;             // shuffle segment base lane
    const int b    = blockIdx.x * BPC + blL;
    const bool active = wrp && (b < Bn);
    const int bload = (b < Bn) ? b : (Bn - 1);
    const int k0   = m * 5;

    // ---- shared init (one warp) ----
    for (int i = tid; i < 100; i += NTHR) {
        int a = i / 10, d = i % 10;
        sh.Wc[a][d]    = Wdd[d*10 + a];    // wddT
        sh.Wc[a][10+d] = Wmd[d*10 + a];    // wmdT
    }
    if (tid < 20) sh.dec[tid/10][tid%10] = decW[tid];

    // ---- per-thread constants ----
    float pw0[5], pw1[5], pw2[5], kb[5], aw[5];
    {
        const float* pwp = pn_w + (size_t)bload*150 + k0;
        #pragma unroll
        for (int j = 0; j < 5; j++) {
            pw0[j] = pwp[j]; pw1[j] = pwp[50+j]; pw2[j] = pwp[100+j];
            kb[j]  = kn_b[k0+j]; aw[j] = apl_w[k0+j];
        }
    }
    const float aplB = apl_b[0];
    const float mbB  = mb_b[m];
    const float wcm  = Wcd[m];
    const float dBm  = dan_b[m];
    const float decb_r = (m < 2) ? decB[m] : 0.f;

    // mbon_dan column m, packed over d-pairs (registers, constant)
    u64 wdm2[5];
    #pragma unroll
    for (int p = 0; p < 5; p++) wdm2[p] = packp(Wdm[(2*p)*10 + m], Wdm[(2*p+1)*10 + m]);

    // ---- plastic state ----
    u64 kcw[25], wac[25];     // wac holds 0.25*wact
    {
        const float* kp = kw0 + (size_t)bload*500 + k0*10;
        const float* ap = wa0 + (size_t)bload*500 + k0*10;
        #pragma unroll
        for (int k = 0; k < 5; k++)
            #pragma unroll
            for (int mp = 0; mp < 5; mp++) {
                kcw[k*5+mp] = *(const u64*)(kp + k*10 + 2*mp);
                float2 w = *(const float2*)(ap + k*10 + 2*mp);
                wac[k*5+mp] = packp(0.25f*w.x, 0.25f*w.y);
            }
    }
    __syncwarp();

    // ---- recurrent state ----
    float kcs[5]  = {0,0,0,0,0};
    float lksS[5] = {0,0,0,0,0};        // lksS = -0.125 * low_kc (pre-scaled)
    u64   ddp[5]  = {0,0,0,0,0};        // dan row (t-1), pre-shuffled at loop tail
    u64   ldp[5]  = {0,0,0,0,0};        // lowdan row (t-1)
    float apl = 0.f, mbon = 0.f, danm = 0.f, lowdan = 0.f;
    float dmod = 0.5f;                  // sigmoid(0) for step 0

    const float ALPHA   = 0.5f/5.5f;
    const float OMA     = 1.0f - 0.5f/5.5f;
    const float ALPHA_S = -0.125f * (0.5f/5.5f);
    const u64   C75     = packs(0.75f);

    u64*         partW0 = &sh.part2[0][slot][0][m];
    const ulonglong2* partR0 = (const ulonglong2*)&sh.part2[0][slotR][m>>1][0];
    float*       psumW0 = &sh.psum[0][slot][0];
    const float* psumR0 = &sh.psum[0][slotR][0];
    const float* wcR    = &sh.Wc[m][0];
    const float* decR   = &sh.dec[(m < 2) ? m : 0][0];

    const float* odp = odor + (size_t)bload*3;
    const float* ctp = ctx  + bload;
    float*       otp = out  + (size_t)b*2 + m;
    const int odS = Bn*3, ctS = Bn, otS = Bn*2;

    // current-step inputs (prefetched one step ahead)
    float o0 = odp[0], o1 = odp[1], o2 = odp[2];
    float cx = ctp[0];
    float n0 = o0, n1 = o1, n2 = o2, ncx = cx;

    for (int t = 0; t < T; t++) {
        const int pb = t & 1;   // part/psum buffer for this step
        u64*         partW = partW0 + pb*200;   // 4*5*10 u64 per buffer
        const ulonglong2* partR = partR0 + pb*100;
        float*       psumW = psumW0 + pb*48;
        const float* psumRd= psumR0 + pb*48;

        // ===== Phase A1: Kenyon + low-pass + kcv partials =====
        float psum = 0.f;
        #pragma unroll
        for (int j = 0; j < 5; j++) {
            float pn  = fmaf(o0, pw0[j], fmaf(o1, pw1[j], o2*pw2[j]));
            float r   = fmaxf(pn - apl + kb[j], 0.f);
            float kcn = fmaf(0.5f, r, 0.5f*kcs[j]);
            kcs[j]  = kcn;
            lksS[j] = fmaf(ALPHA_S, kcn, OMA*lksS[j]);
            psum    = fmaf(kcn, aw[j], psum);
        }
        if (wrp) psumW[m] = psum;
        {
            u64 acc0=0, acc1=0, acc2=0, acc3=0, acc4=0;
            #pragma unroll
            for (int k = 0; k < 5; k++) {
                u64 pk = packs(kcs[k]);
                acc0 = fma2(pk, kcw[k*5+0], acc0);
                acc1 = fma2(pk, kcw[k*5+1], acc1);
                acc2 = fma2(pk, kcw[k*5+2], acc2);
                acc3 = fma2(pk, kcw[k*5+3], acc3);
                acc4 = fma2(pk, kcw[k*5+4], acc4);
            }
            if (wrp) {
                partW[0]  = acc0; partW[10] = acc1; partW[20] = acc2;
                partW[30] = acc3; partW[40] = acc4;
            }
        }
        // ---- prefetch inputs for t+1 ----
        if (t + 1 < T) {
            n0 = odp[odS]; n1 = odp[odS+1]; n2 = odp[odS+2];
            ncx = ctp[ctS];
        }
        __syncwarp();   // the ONLY per-step barrier (part/psum RAW; WAR via double buffer)

        // ===== Phase B: APL, kcv, mbon (dmod precomputed), decay =====
        {
            ulonglong2 s0 = *(const ulonglong2*)(psumRd+0);
            ulonglong2 s1 = *(const ulonglong2*)(psumRd+4);
            u64 s2 = *(const u64*)(psumRd+8);
            u64 s = add2(add2(s0.x, s0.y), add2(s1.x, s1.y));
            s = add2(s, s2);
            apl = fmaf(0.5f, fmaxf(hadd2(s) + aplB, 0.f), 0.5f*apl);
        }
        float kcv;
        {
            ulonglong2 a0 = partR[0], a1 = partR[1], a2 = partR[2],
                       a3 = partR[3], a4 = partR[4];
            u64 s = add2(add2(add2(a0.x,a0.y), add2(a1.x,a1.y)),
                         add2(add2(a2.x,a2.y), add2(a3.x,a3.y)));
            s = add2(s, add2(a4.x, a4.y));
            float lo, hi; unpk(s, lo, hi);
            kcv = (m & 1) ? hi : lo;
        }
        mbon = fmaf(0.5f*dmod, fmaxf(kcv + mbB, 0.f), 0.5f*mbon);
        // decay: kc_w <- 0.75*kc_w + 0.25*wact(t)  (wac pre-syn(t))
        #pragma unroll
        for (int i = 0; i < 25; i++) kcw[i] = fma2(kcw[i], C75, wac[i]);

        // ===== Phase C: mbon via shuffle, DAN (uses old ddp), decoder =====
        float mv[10];
        #pragma unroll
        for (int j = 0; j < 10; j++) mv[j] = __shfl_sync(0xffffffffu, mbon, base + j);
        u64 mbp[5];
        #pragma unroll
        for (int p = 0; p < 5; p++) mbp[p] = packp(mv[2*p], mv[2*p+1]);
        {
            ulonglong2 w0 = *(const ulonglong2*)(wcR+0);   // wdd p0,p1
            ulonglong2 w1 = *(const ulonglong2*)(wcR+4);   // wdd p2,p3
            ulonglong2 w2 = *(const ulonglong2*)(wcR+8);   // wdd p4 | wmd q0
            ulonglong2 w3 = *(const ulonglong2*)(wcR+12);  // wmd q1,q2
            ulonglong2 w4 = *(const ulonglong2*)(wcR+16);  // wmd q3,q4
            u64 c2 = fma2(ddp[0], w0.x, 0ull);
            u64 d2 = fma2(ddp[1], w0.y, 0ull);
            c2 = fma2(ddp[2], w1.x, c2);  d2 = fma2(ddp[3], w1.y, d2);
            c2 = fma2(ddp[4], w2.x, c2);  d2 = fma2(mbp[0], w2.y, d2);
            c2 = fma2(mbp[1], w3.x, c2);  d2 = fma2(mbp[2], w3.y, d2);
            c2 = fma2(mbp[3], w4.x, c2);  d2 = fma2(mbp[4], w4.y, d2);
            float dp = hadd2(add2(c2, d2)) + fmaf(cx, wcm, dBm);
            danm = fmaf(0.5f, fmaxf(dp, 0.f), 0.5f*danm);
        }
        lowdan = fmaf(ALPHA, danm, OMA*lowdan);

        if (active && m < 2) {
            ulonglong2 e0 = *(const ulonglong2*)(decR+0);
            ulonglong2 e1 = *(const ulonglong2*)(decR+4);
            u64 e2 = *(const u64*)(decR+8);
            u64 g2 = fma2(mbp[0], e0.x, 0ull);
            u64 h2 = fma2(mbp[1], e0.y, 0ull);
            g2 = fma2(mbp[2], e1.x, g2);
            h2 = fma2(mbp[3], e1.y, h2);
            g2 = fma2(mbp[4], e2, g2);
            otp[0] = hadd2(add2(g2, h2)) + decb_r;
        }

        // ===== TAIL (pipelined work for step t+1) =====
        // shuffle new dan/lowdan rows
        {
            float dv[10], lv[10];
            #pragma unroll
            for (int j = 0; j < 10; j++) {
                dv[j] = __shfl_sync(0xffffffffu, danm,   base + j);
                lv[j] = __shfl_sync(0xffffffffu, lowdan, base + j);
            }
            #pragma unroll
            for (int p = 0; p < 5; p++) {
                ddp[p] = packp(dv[2*p], dv[2*p+1]);
                ldp[p] = packp(lv[2*p], lv[2*p+1]);
            }
        }
        // dmod for step t+1 (off the next step's critical path)
        {
            u64 a2 = fma2(ddp[0], wdm2[0], 0ull);
            u64 b2 = fma2(ddp[1], wdm2[1], 0ull);
            a2 = fma2(ddp[2], wdm2[2], a2);
            b2 = fma2(ddp[3], wdm2[3], b2);
            a2 = fma2(ddp[4], wdm2[4], a2);
            dmod = 1.f / (1.f + __expf(-hadd2(add2(a2, b2))));
        }
        // plasticity syn(t): wac += 0.125*kc(t)*lowdan(t) - 0.125*lk(t)*dan(t)
        #pragma unroll
        for (int k = 0; k < 5; k++) {
            u64 ka  = packs(0.125f*kcs[k]);
            u64 kb2 = packs(lksS[k]);        // already -0.125*lk
            #pragma unroll
            for (int mp = 0; mp < 5; mp++)
                wac[k*5+mp] = fma2(ka, ldp[mp], fma2(kb2, ddp[mp], wac[k*5+mp]));
        }

        o0 = n0; o1 = n1; o2 = n2; cx = ncx;
        odp += odS; ctp += ctS; otp += otS;
    }
}

extern "C" void kernel_launch(void* const* d_in, const int* in_sizes, int n_in,
                              void* d_out, int out_size)
{
    const float* odor  = (const float*)d_in[0];
    const float* ctx   = (const float*)d_in[1];
    const float* pn_w  = (const float*)d_in[2];
    const float* kn_b  = (const float*)d_in[3];
    const float* apl_w = (const float*)d_in[4];
    const float* apl_b = (const float*)d_in[5];
    const float* Wdm   = (const float*)d_in[6];
    const float* mb_b  = (const float*)d_in[7];
    const float* Wmd   = (const float*)d_in[8];
    const float* Wdd   = (const float*)d_in[9];
    const float* Wcd   = (const float*)d_in[10];
    const float* dan_b = (const float*)d_in[11];
    const float* decW  = (const float*)d_in[12];
    const float* decB  = (const float*)d_in[13];
    const float* kw0   = (const float*)d_in[14];
    const float* wa0   = (const float*)d_in[15];

    const int Bn = in_sizes[14] / 500;          // kc_weight0 = B*50*10
    const int T  = in_sizes[0] / (Bn * 3);      // odor = T*B*3

    const int grid = (Bn + BPC - 1) / BPC;
    fly_kernel<<<grid, NTHR>>>(odor, ctx, pn_w, kn_b, apl_w, apl_b,
                               Wdm, mb_b, Wmd, Wdd, Wcd, dan_b,
                               decW, decB, kw0, wa0,
                               (float*)d_out, Bn, T);
}

// round 16
// speedup vs baseline: 1.0212x; 1.0212x over previous
#include <cuda_runtime.h>

#define MBN  10
#define BPC  3                 // batches per CTA (one warp)
#define NTHR 32

typedef unsigned long long u64;

__device__ __forceinline__ u64 fma2(u64 a, u64 b, u64 c){
    u64 d; asm("fma.rn.f32x2 %0, %1, %2, %3;" : "=l"(d) : "l"(a), "l"(b), "l"(c)); return d;
}
__device__ __forceinline__ u64 add2(u64 a, u64 b){
    u64 d; asm("add.rn.f32x2 %0, %1, %2;" : "=l"(d) : "l"(a), "l"(b)); return d;
}
__device__ __forceinline__ u64 packs(float x){
    u64 r; asm("mov.b64 %0, {%1, %1};" : "=l"(r) : "f"(x)); return r;
}
__device__ __forceinline__ u64 packp(float lo, float hi){
    u64 r; asm("mov.b64 %0, {%1, %2};" : "=l"(r) : "f"(lo), "f"(hi)); return r;
}
__device__ __forceinline__ void unpk(u64 v, float& lo, float& hi){
    asm("mov.b64 {%0, %1}, %2;" : "=f"(lo), "=f"(hi) : "l"(v));
}
__device__ __forceinline__ float hadd2(u64 v){
    float lo, hi; unpk(v, lo, hi); return lo + hi;
}

struct __align__(16) Sh {
    u64   part2[2][4][5][10];  // [buf][slot][mp][j]  kcv partials (double buffered)
    float psum[2][4][12];      // [buf][slot] APL partials
    float Wc[MBN][28];         // [m]: wddT[10] | wmdT[10] | pad
    float dec[2][12];          // decoder rows
};

__global__ void __launch_bounds__(NTHR, 12) fly_kernel(
    const float* __restrict__ odor,  const float* __restrict__ ctx,
    const float* __restrict__ pn_w,  const float* __restrict__ kn_b,
    const float* __restrict__ apl_w, const float* __restrict__ apl_b,
    const float* __restrict__ Wdm,   const float* __restrict__ mb_b,
    const float* __restrict__ Wmd,   const float* __restrict__ Wdd,
    const float* __restrict__ Wcd,   const float* __restrict__ dan_b,
    const float* __restrict__ decW,  const float* __restrict__ decB,
    const float* __restrict__ kw0,   const float* __restrict__ wa0,
    float* __restrict__ out, int Bn, int T)
{
    __shared__ Sh sh;
    const int tid  = threadIdx.x;
    const int m    = tid % MBN;            // m-role AND k-group index
    const int blL  = tid / MBN;            // 0..2 real, 3 dummy
    const int slot = blL;
    const int slotR= (blL == 3) ? 0 : blL;
    const bool wrp = (blL < 3);            // dummy lanes skip smem stores
    const int base = blL * 10;             // shuffle segment base lane
    const int b    = blockIdx.x * BPC + blL;
    const bool active = wrp && (b < Bn);
    const int bload = (b < Bn) ? b : (Bn - 1);
    const int k0   = m * 5;

    // ---- shared init (one warp) ----
    for (int i = tid; i < 100; i += NTHR) {
        int a = i / 10, d = i % 10;
        sh.Wc[a][d]    = Wdd[d*10 + a];    // wddT
        sh.Wc[a][10+d] = Wmd[d*10 + a];    // wmdT
    }
    if (tid < 20) sh.dec[tid/10][tid%10] = decW[tid];

    // ---- per-thread constants ----
    float pw0[5], pw1[5], pw2[5], kb[5], aw[5];
    {
        const float* pwp = pn_w + (size_t)bload*150 + k0;
        #pragma unroll
        for (int j = 0; j < 5; j++) {
            pw0[j] = pwp[j]; pw1[j] = pwp[50+j]; pw2[j] = pwp[100+j];
            kb[j]  = kn_b[k0+j]; aw[j] = apl_w[k0+j];
        }
    }
    const float aplB = apl_b[0];
    const float mbB  = mb_b[m];
    const float wcm  = Wcd[m];
    const float dBm  = dan_b[m];
    const float decb_r = (m < 2) ? decB[m] : 0.f;

    // mbon_dan column m, packed over d-pairs (registers, constant)
    u64 wdm2[5];
    #pragma unroll
    for (int p = 0; p < 5; p++) wdm2[p] = packp(Wdm[(2*p)*10 + m], Wdm[(2*p+1)*10 + m]);

    // ---- plastic state ----
    u64 kcw[25], wac[25];     // wac holds 0.25*wact
    {
        const float* kp = kw0 + (size_t)bload*500 + k0*10;
        const float* ap = wa0 + (size_t)bload*500 + k0*10;
        #pragma unroll
        for (int k = 0; k < 5; k++)
            #pragma unroll
            for (int mp = 0; mp < 5; mp++) {
                kcw[k*5+mp] = *(const u64*)(kp + k*10 + 2*mp);
                float2 w = *(const float2*)(ap + k*10 + 2*mp);
                wac[k*5+mp] = packp(0.25f*w.x, 0.25f*w.y);
            }
    }
    __syncwarp();

    // ---- recurrent state ----
    float kcs[5] = {0,0,0,0,0};
    float lks[5] = {0,0,0,0,0};
    float apl = 0.f, mbon = 0.f, danm = 0.f, lowdan = 0.f;

    const float ALPHA = 0.5f/5.5f;
    const float OMA   = 1.0f - 0.5f/5.5f;
    const u64   C75   = packs(0.75f);

    u64*         partW0 = &sh.part2[0][slot][0][m];
    const ulonglong2* partR0 = (const ulonglong2*)&sh.part2[0][slotR][m>>1][0];
    float*       psumW0 = &sh.psum[0][slot][0];
    const float* psumR0 = &sh.psum[0][slotR][0];
    const float* wcR    = &sh.Wc[m][0];
    const float* decR   = &sh.dec[(m < 2) ? m : 0][0];

    const float* odp = odor + (size_t)bload*3;
    const float* ctp = ctx  + bload;
    float*       otp = out  + (size_t)b*2 + m;
    const int odS = Bn*3, ctS = Bn, otS = Bn*2;

    // current-step inputs (prefetched one step ahead)
    float o0 = odp[0], o1 = odp[1], o2 = odp[2];
    float cx = ctp[0];
    float n0 = o0, n1 = o1, n2 = o2, ncx = cx;

    for (int t = 0; t < T; t++) {
        const int pb = t & 1;   // part/psum buffer for this step
        u64*         partW = partW0 + pb*200;   // 4*5*10 u64 per buffer
        const ulonglong2* partR = partR0 + pb*100;
        float*       psumW = psumW0 + pb*48;
        const float* psumRd= psumR0 + pb*48;

        // ===== Phase A0: shuffle dan/lowdan rows (t-1), apply plasticity(t-1) =====
        float dv[10], lv[10];
        #pragma unroll
        for (int j = 0; j < 10; j++) {
            dv[j] = __shfl_sync(0xffffffffu, danm,   base + j);
            lv[j] = __shfl_sync(0xffffffffu, lowdan, base + j);
        }
        u64 ddp[5], ldp[5];
        #pragma unroll
        for (int p = 0; p < 5; p++) {
            ddp[p] = packp(dv[2*p], dv[2*p+1]);
            ldp[p] = packp(lv[2*p], lv[2*p+1]);
        }
        // wac += 0.125*kc_old*lowdan_old - 0.125*lk_old*dan_old
        #pragma unroll
        for (int k = 0; k < 5; k++) {
            u64 ka  = packs( 0.125f*kcs[k]);
            u64 kb2 = packs(-0.125f*lks[k]);
            #pragma unroll
            for (int mp = 0; mp < 5; mp++)
                wac[k*5+mp] = fma2(ka, ldp[mp], fma2(kb2, ddp[mp], wac[k*5+mp]));
        }

        // ===== Phase A1: Kenyon + low-pass + kcv partials =====
        float psum = 0.f;
        #pragma unroll
        for (int j = 0; j < 5; j++) {
            float pn  = fmaf(o0, pw0[j], fmaf(o1, pw1[j], o2*pw2[j]));
            float r   = fmaxf(pn - apl + kb[j], 0.f);
            float kcn = fmaf(0.5f, r, 0.5f*kcs[j]);
            kcs[j] = kcn;
            lks[j] = fmaf(ALPHA, kcn, OMA*lks[j]);
            psum   = fmaf(kcn, aw[j], psum);
        }
        if (wrp) psumW[m] = psum;
        {
            u64 acc0=0, acc1=0, acc2=0, acc3=0, acc4=0;
            #pragma unroll
            for (int k = 0; k < 5; k++) {
                u64 pk = packs(kcs[k]);
                acc0 = fma2(pk, kcw[k*5+0], acc0);
                acc1 = fma2(pk, kcw[k*5+1], acc1);
                acc2 = fma2(pk, kcw[k*5+2], acc2);
                acc3 = fma2(pk, kcw[k*5+3], acc3);
                acc4 = fma2(pk, kcw[k*5+4], acc4);
            }
            if (wrp) {
                partW[0]  = acc0; partW[10] = acc1; partW[20] = acc2;
                partW[30] = acc3; partW[40] = acc4;
            }
        }
        // ---- prefetch inputs for t+1 (a full step of latency cover) ----
        if (t + 1 < T) {
            n0 = odp[odS]; n1 = odp[odS+1]; n2 = odp[odS+2];
            ncx = ctp[ctS];
        }
        __syncwarp();   // the ONLY per-step barrier (part/psum RAW; WAR via double buffer)

        // ===== Phase B: decay first (independent filler under LDS shadows) =====
        // kc_w <- 0.75*kc_w + 0.25*wact(t)   (A1's dot used pre-decay kcw; wac has syn(t-1))
        #pragma unroll
        for (int i = 0; i < 25; i++) kcw[i] = fma2(kcw[i], C75, wac[i]);

        {
            ulonglong2 s0 = *(const ulonglong2*)(psumRd+0);
            ulonglong2 s1 = *(const ulonglong2*)(psumRd+4);
            u64 s2 = *(const u64*)(psumRd+8);
            u64 s = add2(add2(s0.x, s0.y), add2(s1.x, s1.y));
            s = add2(s, s2);
            apl = fmaf(0.5f, fmaxf(hadd2(s) + aplB, 0.f), 0.5f*apl);
        }
        float dmod;
        {
            u64 a2 = fma2(ddp[0], wdm2[0], 0ull);
            u64 b2 = fma2(ddp[1], wdm2[1], 0ull);
            a2 = fma2(ddp[2], wdm2[2], a2);
            b2 = fma2(ddp[3], wdm2[3], b2);
            a2 = fma2(ddp[4], wdm2[4], a2);
            dmod = 1.f / (1.f + __expf(-hadd2(add2(a2, b2))));
        }
        float kcv;
        {
            ulonglong2 a0 = partR[0], a1 = partR[1], a2 = partR[2],
                       a3 = partR[3], a4 = partR[4];
            u64 s = add2(add2(add2(a0.x,a0.y), add2(a1.x,a1.y)),
                         add2(add2(a2.x,a2.y), add2(a3.x,a3.y)));
            s = add2(s, add2(a4.x, a4.y));
            float lo, hi; unpk(s, lo, hi);
            kcv = (m & 1) ? hi : lo;
        }
        mbon = fmaf(0.5f*dmod, fmaxf(kcv + mbB, 0.f), 0.5f*mbon);

        // ===== Phase C: mbon via shuffle, DAN, traces, decoder =====
        float mv[10];
        #pragma unroll
        for (int j = 0; j < 10; j++) mv[j] = __shfl_sync(0xffffffffu, mbon, base + j);
        u64 mbp[5];
        #pragma unroll
        for (int p = 0; p < 5; p++) mbp[p] = packp(mv[2*p], mv[2*p+1]);
        {
            ulonglong2 w0 = *(const ulonglong2*)(wcR+0);   // wdd p0,p1
            ulonglong2 w1 = *(const ulonglong2*)(wcR+4);   // wdd p2,p3
            ulonglong2 w2 = *(const ulonglong2*)(wcR+8);   // wdd p4 | wmd q0
            ulonglong2 w3 = *(const ulonglong2*)(wcR+12);  // wmd q1,q2
            ulonglong2 w4 = *(const ulonglong2*)(wcR+16);  // wmd q3,q4
            u64 c2 = fma2(ddp[0], w0.x, 0ull);
            u64 d2 = fma2(ddp[1], w0.y, 0ull);
            c2 = fma2(ddp[2], w1.x, c2);  d2 = fma2(ddp[3], w1.y, d2);
            c2 = fma2(ddp[4], w2.x, c2);  d2 = fma2(mbp[0], w2.y, d2);
            c2 = fma2(mbp[1], w3.x, c2);  d2 = fma2(mbp[2], w3.y, d2);
            c2 = fma2(mbp[3], w4.x, c2);  d2 = fma2(mbp[4], w4.y, d2);
            float dp = hadd2(add2(c2, d2)) + fmaf(cx, wcm, dBm);
            danm = fmaf(0.5f, fmaxf(dp, 0.f), 0.5f*danm);
        }
        lowdan = fmaf(ALPHA, danm, OMA*lowdan);

        if (active && m < 2) {
            ulonglong2 e0 = *(const ulonglong2*)(decR+0);
            ulonglong2 e1 = *(const ulonglong2*)(decR+4);
            u64 e2 = *(const u64*)(decR+8);
            u64 g2 = fma2(mbp[0], e0.x, 0ull);
            u64 h2 = fma2(mbp[1], e0.y, 0ull);
            g2 = fma2(mbp[2], e1.x, g2);
            h2 = fma2(mbp[3], e1.y, h2);
            g2 = fma2(mbp[4], e2, g2);
            otp[0] = hadd2(add2(g2, h2)) + decb_r;
        }

        o0 = n0; o1 = n1; o2 = n2; cx = ncx;
        odp += odS; ctp += ctS; otp += otS;
    }
}

extern "C" void kernel_launch(void* const* d_in, const int* in_sizes, int n_in,
                              void* d_out, int out_size)
{
    const float* odor  = (const float*)d_in[0];
    const float* ctx   = (const float*)d_in[1];
    const float* pn_w  = (const float*)d_in[2];
    const float* kn_b  = (const float*)d_in[3];
    const float* apl_w = (const float*)d_in[4];
    const float* apl_b = (const float*)d_in[5];
    const float* Wdm   = (const float*)d_in[6];
    const float* mb_b  = (const float*)d_in[7];
    const float* Wmd   = (const float*)d_in[8];
    const float* Wdd   = (const float*)d_in[9];
    const float* Wcd   = (const float*)d_in[10];
    const float* dan_b = (const float*)d_in[11];
    const float* decW  = (const float*)d_in[12];
    const float* decB  = (const float*)d_in[13];
    const float* kw0   = (const float*)d_in[14];
    const float* wa0   = (const float*)d_in[15];

    const int Bn = in_sizes[14] / 500;          // kc_weight0 = B*50*10
    const int T  = in_sizes[0] / (Bn * 3);      // odor = T*B*3

    const int grid = (Bn + BPC - 1) / BPC;
    fly_kernel<<<grid, NTHR>>>(odor, ctx, pn_w, kn_b, apl_w, apl_b,
                               Wdm, mb_b, Wmd, Wdd, Wcd, dan_b,
                               decW, decB, kw0, wa0,
                               (float*)d_out, Bn, T);
}